// round 1
// baseline (speedup 1.0000x reference)
#include <cuda_runtime.h>
#include <cstdint>

// ---------------------------------------------------------------------------
// AnnularPatchEmbed: out[b,c,j] = fc( sum_{p in ring c} x[b,p] * W[:,p] )
// Rings are disjoint binary masks -> segmented GEMM over ~39.4K masked pixels
// instead of 16x dense work.
// ---------------------------------------------------------------------------

#define IMGSZ 224
#define NPIX  50176      // 224*224
#define NB    64
#define ND    256
#define NC    16
#define NJ    192
#define CK    144        // pixels per GEMM chunk (ring-aligned)
#define MAXC  365        // ceil(50176/144) + 16 upper bound on chunk count

// ------------------------- device scratch (static, no allocs) --------------
__device__ unsigned char g_ring[NPIX];
__device__ int   g_rowCnt[IMGSZ * 17];
__device__ int   g_rowBase[IMGSZ * 16];
__device__ int   g_ringChunkStart[17];
__device__ int   g_chunkRing[MAXC];
__device__ int   g_chunkStart[MAXC];
__device__ int   g_chunkLen[MAXC];
__device__ int   g_numChunks;
__device__ int   g_perm[NPIX];
__device__ float g_partial[(size_t)MAXC * NB * ND];   // ~24 MB

// ------------------------- 1) per-pixel ring id + row histograms -----------
__global__ void k_ring(const float* __restrict__ masks) {
    __shared__ int cnt[17];
    int y = blockIdx.x, lane = threadIdx.x;
    if (lane < 17) cnt[lane] = 0;
    __syncwarp();
    for (int w = 0; w < 7; w++) {
        int p = y * IMGSZ + w * 32 + lane;
        int r = 16;
        #pragma unroll
        for (int c = 0; c < 16; c++)
            if (masks[c * NPIX + p] != 0.0f) r = c;
        g_ring[p] = (unsigned char)r;
        atomicAdd(&cnt[r], 1);
    }
    __syncwarp();
    if (lane < 17) g_rowCnt[y * 17 + lane] = cnt[lane];
}

// ------------------------- 2) offsets, row bases, chunk list ---------------
__global__ void k_scan() {
    __shared__ int tot[17];
    __shared__ int off[17];
    int tid = threadIdx.x;
    if (tid < 17) {
        int s = 0;
        for (int y = 0; y < IMGSZ; y++) s += g_rowCnt[y * 17 + tid];
        tot[tid] = s;
    }
    __syncthreads();
    if (tid == 0) {
        int run = 0;
        for (int c = 0; c < 16; c++) { off[c] = run; run += tot[c]; }
        off[16] = run;
        int nc = 0;
        for (int c = 0; c < 16; c++) {
            g_ringChunkStart[c] = nc;
            int n = tot[c], base = off[c];
            for (int s = 0; s < n; s += CK) {
                if (nc < MAXC) {
                    g_chunkRing[nc]  = c;
                    g_chunkStart[nc] = base + s;
                    g_chunkLen[nc]   = (n - s < CK) ? (n - s) : CK;
                }
                nc++;
            }
        }
        if (nc > MAXC) nc = MAXC;  // cannot happen for these masks; safety
        g_ringChunkStart[16] = nc;
        g_numChunks = nc;
    }
    __syncthreads();
    if (tid < 16) {
        int run = off[tid];
        for (int y = 0; y < IMGSZ; y++) {
            g_rowBase[y * 16 + tid] = run;
            run += g_rowCnt[y * 17 + tid];
        }
    }
}

// ------------------------- 3) deterministic compaction ---------------------
__global__ void k_scatter() {
    __shared__ int cnt[17];
    int y = blockIdx.x, lane = threadIdx.x;
    if (lane < 17) cnt[lane] = 0;
    __syncwarp();
    unsigned lt = (lane == 0) ? 0u : ((1u << lane) - 1u);
    for (int w = 0; w < 7; w++) {
        int p = y * IMGSZ + w * 32 + lane;
        int r = g_ring[p];
        unsigned same = __match_any_sync(0xffffffffu, r);
        int rank = __popc(same & lt);
        int base = cnt[r];
        __syncwarp();
        if (rank == 0) cnt[r] = base + __popc(same);
        __syncwarp();
        if (r < 16) g_perm[g_rowBase[y * 16 + r] + base + rank] = p;
    }
}

// ------------------------- 4) main segmented SGEMM -------------------------
// Grid: (MAXC, 2). CTA = one 144-pixel chunk x one 128-wide d half.
// Tile: 64(b) x 128(d), 256 threads, 8x4 accumulators per thread.
__global__ void __launch_bounds__(256, 2)
k_gemm(const float* __restrict__ X, const float* __restrict__ W) {
    int ch = blockIdx.x;
    if (ch >= g_numChunks) return;
    int d0     = blockIdx.y * 128;
    int kStart = g_chunkStart[ch];
    int kLen   = g_chunkLen[ch];

    __shared__ __align__(16) float xs[2][16 * 68];
    __shared__ __align__(16) float ws[2][16 * 132];
    __shared__ int pSm[CK];

    int tid = threadIdx.x;
    for (int i = tid; i < CK; i += 256)
        pSm[i] = (i < kLen) ? g_perm[kStart + i] : -1;
    __syncthreads();

    int tb = tid >> 5;       // 0..7  -> 8 b-rows each
    int td = tid & 31;       // 0..31 -> 4 d-cols each
    int numTiles = (kLen + 15) >> 4;

    float4 acc[8];
    #pragma unroll
    for (int i = 0; i < 8; i++) acc[i] = make_float4(0.f, 0.f, 0.f, 0.f);

    float xr[4], wr[8];

    auto loadTile = [&](int t) {
        int k0 = t << 4;
        #pragma unroll
        for (int j = 0; j < 4; j++) {
            int i = tid + j * 256;
            int b = i >> 4, kk = i & 15;
            int p = pSm[k0 + kk];
            xr[j] = (p >= 0) ? X[b * NPIX + p] : 0.f;
        }
        #pragma unroll
        for (int j = 0; j < 8; j++) {
            int i = tid + j * 256;
            int d = i >> 4, kk = i & 15;
            int p = pSm[k0 + kk];
            wr[j] = (p >= 0) ? W[(size_t)(d0 + d) * NPIX + p] : 0.f;
        }
    };
    auto storeTile = [&](int buf) {
        #pragma unroll
        for (int j = 0; j < 4; j++) {
            int i = tid + j * 256;
            int b = i >> 4, kk = i & 15;
            xs[buf][kk * 68 + b] = xr[j];
        }
        #pragma unroll
        for (int j = 0; j < 8; j++) {
            int i = tid + j * 256;
            int d = i >> 4, kk = i & 15;
            ws[buf][kk * 132 + d] = wr[j];
        }
    };

    loadTile(0);
    storeTile(0);

    for (int t = 0; t < numTiles; t++) {
        __syncthreads();
        int buf = t & 1;
        if (t + 1 < numTiles) loadTile(t + 1);

        #pragma unroll
        for (int kk = 0; kk < 16; kk++) {
            float4 xa = *(const float4*)&xs[buf][kk * 68 + tb * 8];
            float4 xb = *(const float4*)&xs[buf][kk * 68 + tb * 8 + 4];
            float4 wv = *(const float4*)&ws[buf][kk * 132 + td * 4];
            float xv[8] = {xa.x, xa.y, xa.z, xa.w, xb.x, xb.y, xb.z, xb.w};
            #pragma unroll
            for (int ib = 0; ib < 8; ib++) {
                acc[ib].x = fmaf(xv[ib], wv.x, acc[ib].x);
                acc[ib].y = fmaf(xv[ib], wv.y, acc[ib].y);
                acc[ib].z = fmaf(xv[ib], wv.z, acc[ib].z);
                acc[ib].w = fmaf(xv[ib], wv.w, acc[ib].w);
            }
        }
        __syncthreads();
        if (t + 1 < numTiles) storeTile((t + 1) & 1);
    }

    // write partials: float4 per b-row, coalesced across the warp
    size_t base = (size_t)ch * (NB * ND);
    #pragma unroll
    for (int ib = 0; ib < 8; ib++) {
        int b = tb * 8 + ib;
        *(float4*)&g_partial[base + (size_t)b * ND + d0 + td * 4] = acc[ib];
    }
}

// ------------------------- 5) chunk reduction + fc (256->192) --------------
// Grid: (64 b, 4 ring-groups of 4), 192 threads. out[b,c,j].
__global__ void k_fc(const float* __restrict__ fcw, const float* __restrict__ fcb,
                     float* __restrict__ out) {
    __shared__ __align__(16) float tok[4][260];
    __shared__ __align__(16) float wsm[192 * 36];

    int b = blockIdx.x, cg = blockIdx.y, tid = threadIdx.x;

    for (int i = tid; i < 4 * 256; i += 192) tok[i >> 8][i & 255] = 0.f;
    __syncthreads();

    int c0 = g_ringChunkStart[cg * 4];
    int c1 = g_ringChunkStart[cg * 4 + 4];
    for (int ch = c0; ch < c1; ch++) {
        int lc = g_chunkRing[ch] - cg * 4;
        const float* pp = &g_partial[(size_t)ch * (NB * ND) + (size_t)b * ND];
        tok[lc][tid] += pp[tid];
        if (tid < 64) tok[lc][tid + 192] += pp[tid + 192];
    }
    __syncthreads();

    float acc[4] = {0.f, 0.f, 0.f, 0.f};
    int j = tid;  // 0..191
    for (int dc = 0; dc < 8; dc++) {
        __syncthreads();
        // stage fc_w[:, dc*32 .. +32) transposed-free into padded smem
        #pragma unroll
        for (int t = 0; t < 32; t++) {
            int idx = tid + t * 192;            // 0..6143
            int jj = idx >> 5, dl = idx & 31;
            wsm[jj * 36 + dl] = fcw[jj * 256 + dc * 32 + dl];
        }
        __syncthreads();
        #pragma unroll
        for (int dl = 0; dl < 32; dl += 4) {
            float4 wv = *(const float4*)&wsm[j * 36 + dl];
            #pragma unroll
            for (int cl = 0; cl < 4; cl++) {
                float4 tv = *(const float4*)&tok[cl][dc * 32 + dl];
                acc[cl] += tv.x * wv.x + tv.y * wv.y + tv.z * wv.z + tv.w * wv.w;
            }
        }
    }
    float bias = fcb[j];
    #pragma unroll
    for (int cl = 0; cl < 4; cl++)
        out[((size_t)b * 16 + cg * 4 + cl) * 192 + j] = acc[cl] + bias;
}

// ---------------------------------------------------------------------------
extern "C" void kernel_launch(void* const* d_in, const int* in_sizes, int n_in,
                              void* d_out, int out_size) {
    const float* x     = (const float*)d_in[0];  // [64, 224, 224]
    const float* tw    = (const float*)d_in[1];  // [256, 1, 224, 224]
    const float* fcw   = (const float*)d_in[2];  // [192, 256]
    const float* fcb   = (const float*)d_in[3];  // [192]
    const float* masks = (const float*)d_in[4];  // [16, 224, 224]
    float* out = (float*)d_out;                  // [64, 16, 192]

    k_ring<<<IMGSZ, 32>>>(masks);
    k_scan<<<1, 32>>>();
    k_scatter<<<IMGSZ, 32>>>();
    k_gemm<<<dim3(MAXC, 2), 256>>>(x, tw);
    k_fc<<<dim3(64, 4), 192>>>(fcw, fcb, out);
}

// round 3
// speedup vs baseline: 1.1455x; 1.1455x over previous
#include <cuda_runtime.h>
#include <cstdint>

// ---------------------------------------------------------------------------
// AnnularPatchEmbed: out[b,c,j] = fc( sum_{p in ring c} x[b,p] * W[:,p] )
// Segmented SGEMM over ~39.4K masked pixels; f32x2 packed FMA inner loop.
// ---------------------------------------------------------------------------

#define IMGSZ 224
#define NPIX  50176
#define NB    64
#define ND    256
#define CK    288        // pixels per GEMM chunk (ring-aligned)
#define MAXC  192        // upper bound on chunk count (actual ~150)

#define FMA2(c, a, b) asm("fma.rn.f32x2 %0, %1, %2, %0;" : "+l"(c) : "l"(a), "l"(b))
#define PACK2(p, f)   asm("mov.b64 %0, {%1, %1};" : "=l"(p) : "f"(f))
#define UNPACK2(lo, hi, c) asm("mov.b64 {%0, %1}, %2;" : "=f"(lo), "=f"(hi) : "l"(c))

// ------------------------- device scratch (static, no allocs) --------------
__device__ unsigned char g_ring[NPIX];
__device__ int   g_rowCnt[IMGSZ * 17];
__device__ int   g_rowBase[IMGSZ * 16];
__device__ int   g_ringChunkStart[17];
__device__ int   g_chunkStart[MAXC];
__device__ int   g_chunkLen[MAXC];
__device__ int   g_numChunks;
__device__ int   g_perm[NPIX];
__device__ float g_partial[(size_t)MAXC * NB * ND];   // 12.6 MB

// ------------------------- 1) per-pixel ring id + row histograms -----------
// 56 blocks x 128 threads; warp w handles row blockIdx*4 + w.
__global__ void k_ring(const float* __restrict__ masks) {
    __shared__ int cnt[4][17];
    int w = threadIdx.x >> 5, lane = threadIdx.x & 31;
    int y = blockIdx.x * 4 + w;
    if (lane < 17) cnt[w][lane] = 0;
    __syncwarp();
    for (int g = 0; g < 7; g++) {
        int p = y * IMGSZ + g * 32 + lane;
        int r = 16;
        #pragma unroll
        for (int c = 0; c < 16; c++)
            if (masks[c * NPIX + p] != 0.0f) r = c;
        g_ring[p] = (unsigned char)r;
        atomicAdd(&cnt[w][r], 1);
    }
    __syncwarp();
    if (lane < 17) g_rowCnt[y * 17 + lane] = cnt[w][lane];
}

// ------------------------- 2) offsets, row bases, chunk list ---------------
// 1 block x 512 threads; warp w (w<16) owns ring w; warp scans over rows.
__global__ void k_scan() {
    __shared__ int off[17];
    int tid = threadIdx.x, w = tid >> 5, lane = tid & 31;
    int v[7];
    if (w < 16) {
        int tot = 0;
        #pragma unroll
        for (int g = 0; g < 7; g++) {
            v[g] = g_rowCnt[(g * 32 + lane) * 17 + w];
            tot += v[g];
        }
        #pragma unroll
        for (int d = 16; d; d >>= 1) tot += __shfl_xor_sync(~0u, tot, d);
        if (lane == 0) off[w] = tot;   // ring totals (temp)
    }
    __syncthreads();
    if (tid == 0) {
        int run = 0;
        #pragma unroll
        for (int c = 0; c < 16; c++) { int t = off[c]; off[c] = run; run += t; }
        off[16] = run;
        int nc = 0;
        for (int c = 0; c < 16; c++) {
            g_ringChunkStart[c] = nc;
            int n = off[c + 1] - off[c], base = off[c];
            for (int s = 0; s < n && nc < MAXC; s += CK) {
                g_chunkStart[nc] = base + s;
                g_chunkLen[nc]   = (n - s < CK) ? (n - s) : CK;
                nc++;
            }
        }
        g_ringChunkStart[16] = nc;
        g_numChunks = nc;
    }
    __syncthreads();
    if (w < 16) {
        int carry = off[w];
        #pragma unroll
        for (int g = 0; g < 7; g++) {
            int x = v[g];
            int incl = x;
            #pragma unroll
            for (int d = 1; d < 32; d <<= 1) {
                int n = __shfl_up_sync(~0u, incl, d);
                if (lane >= d) incl += n;
            }
            g_rowBase[(g * 32 + lane) * 16 + w] = carry + incl - x;
            carry += __shfl_sync(~0u, incl, 31);
        }
    }
}

// ------------------------- 3) deterministic compaction ---------------------
__global__ void k_scatter() {
    __shared__ int cnt[4][17];
    int w = threadIdx.x >> 5, lane = threadIdx.x & 31;
    int y = blockIdx.x * 4 + w;
    if (lane < 17) cnt[w][lane] = 0;
    __syncwarp();
    unsigned lt = (lane == 0) ? 0u : ((1u << lane) - 1u);
    for (int g = 0; g < 7; g++) {
        int p = y * IMGSZ + g * 32 + lane;
        int r = g_ring[p];
        unsigned same = __match_any_sync(0xffffffffu, r);
        int rank = __popc(same & lt);
        int base = cnt[w][r];
        __syncwarp();
        if (rank == 0) cnt[w][r] = base + __popc(same);
        __syncwarp();
        if (r < 16) g_perm[g_rowBase[y * 16 + r] + base + rank] = p;
    }
}

// ------------------------- 4) main segmented SGEMM (f32x2) -----------------
// Grid (MAXC, 2). CTA = one 288-pixel chunk x one 128-wide d half.
// 64(b) x 128(d) tile, 256 threads, 8b x 4d accs packed as 4 b-pairs x 4 d.
__global__ void __launch_bounds__(256, 2)
k_gemm(const float* __restrict__ X, const float* __restrict__ W) {
    int ch = blockIdx.x;
    if (ch >= g_numChunks) return;
    int d0     = blockIdx.y * 128;
    int kStart = g_chunkStart[ch];
    int kLen   = g_chunkLen[ch];

    __shared__ __align__(16) float xs[2][16 * 68];
    __shared__ __align__(16) float ws[2][16 * 132];
    __shared__ int pSm[CK];

    int tid = threadIdx.x;
    for (int i = tid; i < CK; i += 256)
        pSm[i] = (i < kLen) ? g_perm[kStart + i] : -1;
    __syncthreads();

    int tb = tid >> 5;       // 0..7  -> 8 b-rows each (4 pairs)
    int td = tid & 31;       // 0..31 -> 4 d-cols each
    int numTiles = (kLen + 15) >> 4;

    unsigned long long acc[4][4];     // [b-pair][d]
    #pragma unroll
    for (int i = 0; i < 4; i++)
        #pragma unroll
        for (int j = 0; j < 4; j++) acc[i][j] = 0ULL;

    float xr[4], wr[8];

    auto loadTile = [&](int t) {
        int k0 = t << 4;
        #pragma unroll
        for (int j = 0; j < 4; j++) {
            int i = tid + j * 256;
            int b = i >> 4, kk = i & 15;
            int p = pSm[k0 + kk];
            xr[j] = (p >= 0) ? X[b * NPIX + p] : 0.f;
        }
        #pragma unroll
        for (int j = 0; j < 8; j++) {
            int i = tid + j * 256;
            int d = i >> 4, kk = i & 15;
            int p = pSm[k0 + kk];
            wr[j] = (p >= 0) ? W[(size_t)(d0 + d) * NPIX + p] : 0.f;
        }
    };
    auto storeTile = [&](int buf) {
        #pragma unroll
        for (int j = 0; j < 4; j++) {
            int i = tid + j * 256;
            int b = i >> 4, kk = i & 15;
            xs[buf][kk * 68 + b] = xr[j];
        }
        #pragma unroll
        for (int j = 0; j < 8; j++) {
            int i = tid + j * 256;
            int d = i >> 4, kk = i & 15;
            ws[buf][kk * 132 + d] = wr[j];
        }
    };

    loadTile(0);
    storeTile(0);

    for (int t = 0; t < numTiles; t++) {
        __syncthreads();
        int buf = t & 1;
        if (t + 1 < numTiles) loadTile(t + 1);

        #pragma unroll
        for (int kk = 0; kk < 16; kk++) {
            const float* xrow = &xs[buf][kk * 68 + tb * 8];
            ulonglong2 xa = *(const ulonglong2*)xrow;         // b-pairs 0,1
            ulonglong2 xb = *(const ulonglong2*)(xrow + 4);   // b-pairs 2,3
            float4 wv = *(const float4*)&ws[buf][kk * 132 + td * 4];
            unsigned long long wp0, wp1, wp2, wp3;
            PACK2(wp0, wv.x); PACK2(wp1, wv.y); PACK2(wp2, wv.z); PACK2(wp3, wv.w);
            FMA2(acc[0][0], xa.x, wp0); FMA2(acc[0][1], xa.x, wp1);
            FMA2(acc[0][2], xa.x, wp2); FMA2(acc[0][3], xa.x, wp3);
            FMA2(acc[1][0], xa.y, wp0); FMA2(acc[1][1], xa.y, wp1);
            FMA2(acc[1][2], xa.y, wp2); FMA2(acc[1][3], xa.y, wp3);
            FMA2(acc[2][0], xb.x, wp0); FMA2(acc[2][1], xb.x, wp1);
            FMA2(acc[2][2], xb.x, wp2); FMA2(acc[2][3], xb.x, wp3);
            FMA2(acc[3][0], xb.y, wp0); FMA2(acc[3][1], xb.y, wp1);
            FMA2(acc[3][2], xb.y, wp2); FMA2(acc[3][3], xb.y, wp3);
        }
        __syncthreads();
        if (t + 1 < numTiles) storeTile((t + 1) & 1);
    }

    // unpack + write partials (float4 per b-row)
    size_t base = (size_t)ch * (NB * ND);
    #pragma unroll
    for (int bp = 0; bp < 4; bp++) {
        float lo0, hi0, lo1, hi1, lo2, hi2, lo3, hi3;
        UNPACK2(lo0, hi0, acc[bp][0]);
        UNPACK2(lo1, hi1, acc[bp][1]);
        UNPACK2(lo2, hi2, acc[bp][2]);
        UNPACK2(lo3, hi3, acc[bp][3]);
        int b0 = tb * 8 + bp * 2;
        float4 vlo = make_float4(lo0, lo1, lo2, lo3);
        float4 vhi = make_float4(hi0, hi1, hi2, hi3);
        *(float4*)&g_partial[base + (size_t)b0 * ND + d0 + td * 4] = vlo;
        *(float4*)&g_partial[base + (size_t)(b0 + 1) * ND + d0 + td * 4] = vhi;
    }
}

// ------------------------- 5) fused chunk-reduce + fc (256->192) -----------
// Grid 64 (one block per b), 256 threads. Reduce: thread = one d over all c.
// Then fc with f32x2 packed over ring-pairs.
__global__ void __launch_bounds__(256)
k_fc(const float* __restrict__ fcw, const float* __restrict__ fcb,
     float* __restrict__ out) {
    __shared__ __align__(16) float tok[256 * 20];   // [d][c] padded to 20
    __shared__ int cs[17];

    int b = blockIdx.x, tid = threadIdx.x;
    if (tid < 17) cs[tid] = g_ringChunkStart[tid];
    __syncthreads();

    // parallel reduction over chunks: coalesced across d = tid
    {
        size_t brow = (size_t)b * ND + tid;
        #pragma unroll 1
        for (int c = 0; c < 16; c++) {
            int c0 = cs[c], c1 = cs[c + 1];
            float s0 = 0.f, s1 = 0.f;
            int ch = c0;
            for (; ch + 1 < c1; ch += 2) {
                s0 += g_partial[(size_t)ch * (NB * ND) + brow];
                s1 += g_partial[(size_t)(ch + 1) * (NB * ND) + brow];
            }
            if (ch < c1) s0 += g_partial[(size_t)ch * (NB * ND) + brow];
            tok[tid * 20 + c] = s0 + s1;
        }
    }
    __syncthreads();

    if (tid < 192) {
        int j = tid;
        unsigned long long acc[8];
        #pragma unroll
        for (int q = 0; q < 8; q++) acc[q] = 0ULL;

        const float4* fw4 = (const float4*)(fcw + (size_t)j * ND);
        #pragma unroll 4
        for (int d4 = 0; d4 < 64; d4++) {
            float4 wv = fw4[d4];
            #pragma unroll
            for (int s = 0; s < 4; s++) {
                int d = d4 * 4 + s;
                float w = (s == 0) ? wv.x : (s == 1) ? wv.y : (s == 2) ? wv.z : wv.w;
                unsigned long long wp;
                PACK2(wp, w);
                const ulonglong2* tp = (const ulonglong2*)&tok[d * 20];
                ulonglong2 t0 = tp[0], t1 = tp[1], t2 = tp[2], t3 = tp[3];
                FMA2(acc[0], t0.x, wp); FMA2(acc[1], t0.y, wp);
                FMA2(acc[2], t1.x, wp); FMA2(acc[3], t1.y, wp);
                FMA2(acc[4], t2.x, wp); FMA2(acc[5], t2.y, wp);
                FMA2(acc[6], t3.x, wp); FMA2(acc[7], t3.y, wp);
            }
        }
        float bias = fcb[j];
        #pragma unroll
        for (int q = 0; q < 8; q++) {
            float lo, hi;
            UNPACK2(lo, hi, acc[q]);
            out[((size_t)b * 16 + 2 * q) * 192 + j]     = lo + bias;
            out[((size_t)b * 16 + 2 * q + 1) * 192 + j] = hi + bias;
        }
    }
}

// ---------------------------------------------------------------------------
extern "C" void kernel_launch(void* const* d_in, const int* in_sizes, int n_in,
                              void* d_out, int out_size) {
    const float* x     = (const float*)d_in[0];  // [64, 224, 224]
    const float* tw    = (const float*)d_in[1];  // [256, 1, 224, 224]
    const float* fcw   = (const float*)d_in[2];  // [192, 256]
    const float* fcb   = (const float*)d_in[3];  // [192]
    const float* masks = (const float*)d_in[4];  // [16, 224, 224]
    float* out = (float*)d_out;                  // [64, 16, 192]

    k_ring<<<56, 128>>>(masks);
    k_scan<<<1, 512>>>();
    k_scatter<<<56, 128>>>();
    k_gemm<<<dim3(MAXC, 2), 256>>>(x, tw);
    k_fc<<<64, 256>>>(fcw, fcb, out);
}